// round 13
// baseline (speedup 1.0000x reference)
#include <cuda_runtime.h>
#include <cuda_bf16.h>
#include <cuda_fp16.h>
#include <cstdint>
#include <cstddef>

// LINKX forward: fp16 mma.sync GEMMs (fp32 accum), fp16 activations
// (comb/agg stored as half -> L2-resident), CSR fp16 gather, x-branch
// MLP overlapped on a side stream with fill+gather.
//   hx = relu(x@wx1+bx1)@wx2+bx2                  (side stream)
//   agg = segment_mean(adj_embed[src] -> dst)     (CSR build + fp16 gather)
//   ha = relu(agg@wa1+ba1)@wa2+ba2
//   h  = relu(relu([hx,ha]@ww1+bw1) + hx + ha)    (join)
//   out = h@wc+bc

#define NN     100000
#define EE     1600000
#define INDIM  256
#define HID    128
#define NC     40

#define NBLK_SCAN 98   // ceil(NN/1024)

// ---------------- static scratch ----------------
__device__ uint32_t g_comb[(size_t)NN * 128];  // [hx | ha] fp16, row = 128 uints
__device__ uint32_t g_agg [(size_t)NN * 64];   // neighbour mean fp16, row = 64 uints
__device__ uint32_t g_z16 [(size_t)NN * 64];   // adj_embed fp16
__device__ uint32_t g_wp  [59904];             // fragment-packed fp16 weights
__device__ int      g_cnt [NN];
__device__ int      g_start[NN];
__device__ int      g_cur [NN];
__device__ int      g_bsum[NBLK_SCAN];
__device__ int      g_srcs[EE];

// packed-weight uint offsets (1 uint = half2)
#define WP_X1 0
#define WP_X2 16384
#define WP_A1 24576
#define WP_A2 32768
#define WP_W1 40960
#define WP_C  57344

// ---------------- helpers ----------------
__device__ __forceinline__ float relu(float v) { return fmaxf(v, 0.0f); }

// m16n8k16 fp16 MMA, fp32 accum
__device__ __forceinline__ void mma16(float* d, const uint32_t* a, const uint32_t* b) {
    asm volatile("mma.sync.aligned.m16n8k16.row.col.f32.f16.f16.f32 "
                 "{%0,%1,%2,%3}, {%4,%5,%6,%7}, {%8,%9}, {%0,%1,%2,%3};"
                 : "+f"(d[0]), "+f"(d[1]), "+f"(d[2]), "+f"(d[3])
                 : "r"(a[0]), "r"(a[1]), "r"(a[2]), "r"(a[3]),
                   "r"(b[0]), "r"(b[1]));
}

// Fragment-packed fp16 A layout (tile 128 rows x K cols), uint granularity:
//   uint idx = ((s*8 + R/16)*32 + (R%8)*4 + ((k%8)>>1))*4 + ((k>>3)&1)*2 + ((R>>3)&1)
__device__ __forceinline__ void packH(uint32_t* P, int R, int Ck, float v0, float v1) {
    int s = Ck >> 4, khi = (Ck >> 3) & 1, kp = (Ck & 7) >> 1;
    int mt = R >> 4, rg = (R >> 3) & 1, row8 = R & 7;
    __half2 h = __floats2half2_rn(v0, v1);
    P[(((s * 8 + mt) * 32 + row8 * 4 + kp) << 2) + khi * 2 + rg] = *(uint32_t*)&h;
}

// ---------------- weight packing (B-fragment fp16 layout) ----------------
__device__ __forceinline__ void pack_one_h(const float* __restrict__ W,
                                           uint32_t* __restrict__ Pu, int idx) {
    int k = idx >> 7, n = idx & 127;
    int uidx = (((k >> 4) * 16 + (n >> 3)) * 32 + (n & 7) * 4 + ((k & 7) >> 1)) * 2
             + ((k >> 3) & 1);
    ((uint16_t*)Pu)[uidx * 2 + (k & 1)] = __half_as_ushort(__float2half_rn(W[idx]));
}

__global__ void pack_all(const float* __restrict__ wx1, const float* __restrict__ wx2,
                         const float* __restrict__ wa1, const float* __restrict__ wa2,
                         const float* __restrict__ ww1, const float* __restrict__ wc,
                         uint32_t* __restrict__ wp) {
    int i = blockIdx.x * blockDim.x + threadIdx.x;
    if (i < NN) g_cnt[i] = 0;
    if (i < 32768)       pack_one_h(wx1, wp + WP_X1, i);
    else if (i < 49152)  pack_one_h(wx2, wp + WP_X2, i - 32768);
    else if (i < 65536)  pack_one_h(wa1, wp + WP_A1, i - 49152);
    else if (i < 81920)  pack_one_h(wa2, wp + WP_A2, i - 65536);
    else if (i < 114688) pack_one_h(ww1, wp + WP_W1, i - 81920);
    else if (i < 119808) {
        int idx = i - 114688;
        int k = idx / 40, n = idx % 40;
        int uidx = (((k >> 4) * 5 + (n >> 3)) * 32 + (n & 7) * 4 + ((k & 7) >> 1)) * 2
                 + ((k >> 3) & 1);
        ((uint16_t*)(wp + WP_C))[uidx * 2 + (k & 1)] =
            __half_as_ushort(__float2half_rn(wc[idx]));
    }
}

// ---------------- prep: adj_embed -> fp16  AND  degree histogram ------------
__global__ void prep_kernel(const float* __restrict__ z, const int* __restrict__ ei) {
    int i = blockIdx.x * blockDim.x + threadIdx.x;
    if (i < EE / 4) {
        int4 d = *(const int4*)(ei + EE + i * 4);
        atomicAdd(&g_cnt[d.x], 1);
        atomicAdd(&g_cnt[d.y], 1);
        atomicAdd(&g_cnt[d.z], 1);
        atomicAdd(&g_cnt[d.w], 1);
    }
    if (i >= NN * (HID / 4)) return;
    float4 v = ((const float4*)z)[i];
    __half2 h0 = __floats2half2_rn(v.x, v.y);
    __half2 h1 = __floats2half2_rn(v.z, v.w);
    uint2 u;
    u.x = *(uint32_t*)&h0;
    u.y = *(uint32_t*)&h1;
    ((uint2*)g_z16)[i] = u;
}

// ---------------- CSR build ----------------
__global__ void scan1() {
    __shared__ int sh[1024];
    int t  = threadIdx.x;
    int gi = blockIdx.x * 1024 + t;
    int v  = (gi < NN) ? g_cnt[gi] : 0;
    sh[t] = v;
    __syncthreads();
#pragma unroll
    for (int o = 1; o < 1024; o <<= 1) {
        int u = (t >= o) ? sh[t - o] : 0;
        __syncthreads();
        sh[t] += u;
        __syncthreads();
    }
    if (gi < NN) g_start[gi] = sh[t];
    if (t == 1023) g_bsum[blockIdx.x] = sh[1023];
}

__global__ void scan2() {
    __shared__ int sh[128];
    int t = threadIdx.x;
    int v = (t < NBLK_SCAN) ? g_bsum[t] : 0;
    sh[t] = v;
    __syncthreads();
#pragma unroll
    for (int o = 1; o < 128; o <<= 1) {
        int u = (t >= o) ? sh[t - o] : 0;
        __syncthreads();
        sh[t] += u;
        __syncthreads();
    }
    if (t < NBLK_SCAN) g_bsum[t] = sh[t] - v;
}

__global__ void scan3() {
    int i = blockIdx.x * blockDim.x + threadIdx.x;
    if (i >= NN) return;
    int st = g_start[i] + g_bsum[i >> 10] - g_cnt[i];
    g_start[i] = st;
    g_cur[i]   = st;
}

__global__ void fill_kernel(const int* __restrict__ ei) {
    int t = blockIdx.x * blockDim.x + threadIdx.x;
    int e = t * 4;
    if (e + 4 > EE) return;
    int4 s = *(const int4*)(ei + e);
    int4 d = *(const int4*)(ei + EE + e);
    g_srcs[atomicAdd(&g_cur[d.x], 1)] = s.x;
    g_srcs[atomicAdd(&g_cur[d.y], 1)] = s.y;
    g_srcs[atomicAdd(&g_cur[d.z], 1)] = s.z;
    g_srcs[atomicAdd(&g_cur[d.w], 1)] = s.w;
}

// ---------------- gather: one warp per node, fp16 in/out, fp32 accum --------
__global__ __launch_bounds__(256)
void gather_kernel() {
    int gw   = (blockIdx.x * blockDim.x + threadIdx.x) >> 5;
    int lane = threadIdx.x & 31;
    if (gw >= NN) return;
    int beg = g_start[gw];
    int dg  = g_cnt[gw];

    float2 a0 = make_float2(0.f, 0.f), b0 = make_float2(0.f, 0.f);
    float2 a1 = make_float2(0.f, 0.f), b1 = make_float2(0.f, 0.f);
    float2 a2 = make_float2(0.f, 0.f), b2 = make_float2(0.f, 0.f);
    float2 a3 = make_float2(0.f, 0.f), b3 = make_float2(0.f, 0.f);

    int e = 0;
    for (; e + 4 <= dg; e += 4) {
        int s0 = g_srcs[beg + e];
        int s1 = g_srcs[beg + e + 1];
        int s2 = g_srcs[beg + e + 2];
        int s3 = g_srcs[beg + e + 3];
        uint2 u0 = *((const uint2*)(g_z16 + (size_t)s0 * 64) + lane);
        uint2 u1 = *((const uint2*)(g_z16 + (size_t)s1 * 64) + lane);
        uint2 u2 = *((const uint2*)(g_z16 + (size_t)s2 * 64) + lane);
        uint2 u3 = *((const uint2*)(g_z16 + (size_t)s3 * 64) + lane);
        float2 f;
        f = __half22float2(*(__half2*)&u0.x); a0.x += f.x; a0.y += f.y;
        f = __half22float2(*(__half2*)&u0.y); b0.x += f.x; b0.y += f.y;
        f = __half22float2(*(__half2*)&u1.x); a1.x += f.x; a1.y += f.y;
        f = __half22float2(*(__half2*)&u1.y); b1.x += f.x; b1.y += f.y;
        f = __half22float2(*(__half2*)&u2.x); a2.x += f.x; a2.y += f.y;
        f = __half22float2(*(__half2*)&u2.y); b2.x += f.x; b2.y += f.y;
        f = __half22float2(*(__half2*)&u3.x); a3.x += f.x; a3.y += f.y;
        f = __half22float2(*(__half2*)&u3.y); b3.x += f.x; b3.y += f.y;
    }
    for (; e < dg; e++) {
        int s0 = g_srcs[beg + e];
        uint2 u0 = *((const uint2*)(g_z16 + (size_t)s0 * 64) + lane);
        float2 f;
        f = __half22float2(*(__half2*)&u0.x); a0.x += f.x; a0.y += f.y;
        f = __half22float2(*(__half2*)&u0.y); b0.x += f.x; b0.y += f.y;
    }

    float inv = 1.0f / (float)max(dg, 1);
    __half2 h0 = __floats2half2_rn((a0.x + a1.x + a2.x + a3.x) * inv,
                                   (a0.y + a1.y + a2.y + a3.y) * inv);
    __half2 h1 = __floats2half2_rn((b0.x + b1.x + b2.x + b3.x) * inv,
                                   (b0.y + b1.y + b2.y + b3.y) * inv);
    uint2 u;
    u.x = *(uint32_t*)&h0;
    u.y = *(uint32_t*)&h1;
    *((uint2*)(g_agg + (size_t)gw * 64) + lane) = u;
}

// ---------------- fused 2-layer MLP (fp16 MMA, templated A dtype) ----------
// Cout(fp16) = relu(A@W1+b1)@W2 + b2.  AHALF=0: A fp32 [M,K1]; AHALF=1: A fp16.
// SMEM (8192 uints = 32KB): double-buffered mainloop tiles; reused as Pk.
#define MLP_SMEM (8192 * 4)

template <int AHALF>
__global__ __launch_bounds__(256, 2)
void fused_mlp(const void* __restrict__ Av, const uint32_t* __restrict__ W1p,
               const float* __restrict__ b1, const uint32_t* __restrict__ W2p,
               const float* __restrict__ b2, uint32_t* __restrict__ Cout,
               int K1, int ldcu) {
    extern __shared__ uint32_t smu[];
    uint32_t* Pk = smu;

    int tid  = threadIdx.x;
    int lane = tid & 31;
    int w    = tid >> 5;
    int wm   = w >> 1;
    int wn   = w & 1;
    int group = lane >> 2;
    int tq    = lane & 3;
    int row_base = blockIdx.x * 128;
    const int M = NN;

    float acc[2][8][4];
#pragma unroll
    for (int i = 0; i < 2; i++)
#pragma unroll
        for (int j = 0; j < 8; j++)
#pragma unroll
            for (int q = 0; q < 4; q++) acc[i][j][q] = 0.0f;

    int wf_r[4], wf_c4[4];
#pragma unroll
    for (int i = 0; i < 4; i++) {
        int f = tid + i * 256;
        wf_r[i]  = f >> 3;
        wf_c4[i] = (f & 7) << 2;
    }

    float4 stA[4];
    uint2  stAu[4];
    uint4  stB[2];
    int nchunk = K1 >> 5;

    auto load_chunk = [&](int c) {
#pragma unroll
        for (int i = 0; i < 4; i++) {
            int gr = row_base + wf_r[i];
            if (AHALF) {
                uint2 u = make_uint2(0u, 0u);
                if (gr < M)
                    u = *(const uint2*)((const uint32_t*)Av +
                        (size_t)gr * (K1 >> 1) + (c << 4) + (wf_c4[i] >> 1));
                stAu[i] = u;
            } else {
                float4 v = make_float4(0.f, 0.f, 0.f, 0.f);
                if (gr < M)
                    v = *(const float4*)((const float*)Av +
                        (size_t)gr * K1 + (c << 5) + wf_c4[i]);
                stA[i] = v;
            }
        }
        const uint4* bsrc = (const uint4*)(W1p + c * 2048);
#pragma unroll
        for (int i = 0; i < 2; i++) stB[i] = bsrc[tid + i * 256];
    };

    auto store_chunk = [&](int b) {
        uint32_t* Ab = smu + b * 4096;
        uint32_t* Bb = smu + b * 4096 + 2048;
#pragma unroll
        for (int i = 0; i < 4; i++) {
            int r = wf_r[i], c4 = wf_c4[i];
            int sl  = c4 >> 4;
            int khi = (c4 >> 3) & 1;
            int kp  = (c4 & 7) >> 1;
            int mt  = r >> 4, rg = (r >> 3) & 1, row8 = r & 7;
            uint32_t base = (((sl * 8 + mt) * 32 + row8 * 4 + kp) << 2) + khi * 2 + rg;
            if (AHALF) {
                Ab[base]     = stAu[i].x;
                Ab[base + 4] = stAu[i].y;
            } else {
                __half2 h0 = __floats2half2_rn(stA[i].x, stA[i].y);
                __half2 h1 = __floats2half2_rn(stA[i].z, stA[i].w);
                Ab[base]     = *(uint32_t*)&h0;
                Ab[base + 4] = *(uint32_t*)&h1;
            }
        }
        ((uint4*)Bb)[tid]       = stB[0];
        ((uint4*)Bb)[tid + 256] = stB[1];
    };

    load_chunk(0);
    store_chunk(0);
    __syncthreads();

    for (int c = 0; c < nchunk; c++) {
        int b = c & 1;
        if (c + 1 < nchunk) load_chunk(c + 1);

        const uint32_t* Ab = smu + b * 4096;
        const uint32_t* Bb = smu + b * 4096 + 2048;
#pragma unroll
        for (int sl = 0; sl < 2; sl++) {
            uint4 af[2];
#pragma unroll
            for (int mt = 0; mt < 2; mt++)
                af[mt] = *(const uint4*)(Ab + ((sl * 8 + wm * 2 + mt) * 32 + lane) * 4);
            uint2 bf[8];
#pragma unroll
            for (int nt = 0; nt < 8; nt++)
                bf[nt] = *(const uint2*)(Bb + ((sl * 16 + wn * 8 + nt) * 32 + lane) * 2);
#pragma unroll
            for (int mt = 0; mt < 2; mt++)
#pragma unroll
                for (int nt = 0; nt < 8; nt++)
                    mma16(acc[mt][nt], (const uint32_t*)&af[mt], (const uint32_t*)&bf[nt]);
        }

        if (c + 1 < nchunk) store_chunk((c + 1) & 1);
        __syncthreads();
    }

    // stage-1 epilogue: relu(acc+b1) -> fragment-packed fp16 SMEM (aliased)
#pragma unroll
    for (int mt = 0; mt < 2; mt++) {
        int Rb = wm * 32 + mt * 16 + group;
#pragma unroll
        for (int nt = 0; nt < 8; nt++) {
            int col = wn * 64 + nt * 8 + tq * 2;
            float2 bv = *(const float2*)(b1 + col);
            packH(Pk, Rb,     col, relu(acc[mt][nt][0] + bv.x),
                                   relu(acc[mt][nt][1] + bv.y));
            packH(Pk, Rb + 8, col, relu(acc[mt][nt][2] + bv.x),
                                   relu(acc[mt][nt][3] + bv.y));
        }
    }
    __syncthreads();

    // stage 2: packed A (K=128, 8 steps) @ W2 (fragments from global / L1)
    float acc2[2][8][4];
#pragma unroll
    for (int i = 0; i < 2; i++)
#pragma unroll
        for (int j = 0; j < 8; j++)
#pragma unroll
            for (int q = 0; q < 4; q++) acc2[i][j][q] = 0.0f;

    const uint2* W2f = (const uint2*)W2p;
#pragma unroll
    for (int s = 0; s < 8; s++) {
        uint4 af[2];
#pragma unroll
        for (int mt = 0; mt < 2; mt++)
            af[mt] = *(const uint4*)(Pk + ((s * 8 + wm * 2 + mt) * 32 + lane) * 4);
        uint2 bf[8];
#pragma unroll
        for (int nt = 0; nt < 8; nt++)
            bf[nt] = __ldg(W2f + (s * 16 + wn * 8 + nt) * 32 + lane);
#pragma unroll
        for (int mt = 0; mt < 2; mt++)
#pragma unroll
            for (int nt = 0; nt < 8; nt++)
                mma16(acc2[mt][nt], (const uint32_t*)&af[mt], (const uint32_t*)&bf[nt]);
    }

    // stage-2 epilogue: + b2, store fp16 to Cout
#pragma unroll
    for (int mt = 0; mt < 2; mt++) {
        int r0 = row_base + wm * 32 + mt * 16 + group;
#pragma unroll
        for (int nt = 0; nt < 8; nt++) {
            int col = wn * 64 + nt * 8 + tq * 2;
            float2 bv = *(const float2*)(b2 + col);
            if (r0 < M) {
                __half2 h = __floats2half2_rn(acc2[mt][nt][0] + bv.x,
                                              acc2[mt][nt][1] + bv.y);
                Cout[(size_t)r0 * ldcu + (col >> 1)] = *(uint32_t*)&h;
            }
            if (r0 + 8 < M) {
                __half2 h = __floats2half2_rn(acc2[mt][nt][2] + bv.x,
                                              acc2[mt][nt][3] + bv.y);
                Cout[(size_t)(r0 + 8) * ldcu + (col >> 1)] = *(uint32_t*)&h;
            }
        }
    }
}

// ---------------- fused final: concat-MLP + residual + classifier ----------
// comb fp16 [M, 256 halves]. h = relu(relu(comb@ww1+bw1) + hx + ha); out=h@wc+bc
#define FIN_SMEM ((8192 + 2560) * 4)

__global__ __launch_bounds__(256, 2)
void fused_final(const uint32_t* __restrict__ comb, const uint32_t* __restrict__ W1p,
                 const float* __restrict__ b1, const uint32_t* __restrict__ Wcp,
                 const float* __restrict__ bc, float* __restrict__ out) {
    extern __shared__ uint32_t smu[];
    uint32_t* Pk  = smu;
    uint32_t* Wcs = smu + 8192;

    int tid  = threadIdx.x;
    int lane = tid & 31;
    int w    = tid >> 5;
    int wm   = w >> 1;
    int wn   = w & 1;
    int group = lane >> 2;
    int tq    = lane & 3;
    int row_base = blockIdx.x * 128;
    const int M = NN;

    for (int i = tid; i < 640; i += 256)
        ((uint4*)Wcs)[i] = ((const uint4*)Wcp)[i];

    float acc[2][8][4];
#pragma unroll
    for (int i = 0; i < 2; i++)
#pragma unroll
        for (int j = 0; j < 8; j++)
#pragma unroll
            for (int q = 0; q < 4; q++) acc[i][j][q] = 0.0f;

    int wf_r[4], wf_c4[4];
#pragma unroll
    for (int i = 0; i < 4; i++) {
        int f = tid + i * 256;
        wf_r[i]  = f >> 3;
        wf_c4[i] = (f & 7) << 2;
    }

    uint2 stAu[4];
    uint4 stB[2];
    const int nchunk = 8;

    auto load_chunk = [&](int c) {
#pragma unroll
        for (int i = 0; i < 4; i++) {
            int gr = row_base + wf_r[i];
            uint2 u = make_uint2(0u, 0u);
            if (gr < M)
                u = *(const uint2*)(comb + (size_t)gr * 128 + (c << 4) + (wf_c4[i] >> 1));
            stAu[i] = u;
        }
        const uint4* bsrc = (const uint4*)(W1p + c * 2048);
#pragma unroll
        for (int i = 0; i < 2; i++) stB[i] = bsrc[tid + i * 256];
    };

    auto store_chunk = [&](int b) {
        uint32_t* Ab = smu + b * 4096;
        uint32_t* Bb = smu + b * 4096 + 2048;
#pragma unroll
        for (int i = 0; i < 4; i++) {
            int r = wf_r[i], c4 = wf_c4[i];
            int sl  = c4 >> 4;
            int khi = (c4 >> 3) & 1;
            int kp  = (c4 & 7) >> 1;
            int mt  = r >> 4, rg = (r >> 3) & 1, row8 = r & 7;
            uint32_t base = (((sl * 8 + mt) * 32 + row8 * 4 + kp) << 2) + khi * 2 + rg;
            Ab[base]     = stAu[i].x;
            Ab[base + 4] = stAu[i].y;
        }
        ((uint4*)Bb)[tid]       = stB[0];
        ((uint4*)Bb)[tid + 256] = stB[1];
    };

    load_chunk(0);
    store_chunk(0);
    __syncthreads();

    for (int c = 0; c < nchunk; c++) {
        int b = c & 1;
        if (c + 1 < nchunk) load_chunk(c + 1);

        const uint32_t* Ab = smu + b * 4096;
        const uint32_t* Bb = smu + b * 4096 + 2048;
#pragma unroll
        for (int sl = 0; sl < 2; sl++) {
            uint4 af[2];
#pragma unroll
            for (int mt = 0; mt < 2; mt++)
                af[mt] = *(const uint4*)(Ab + ((sl * 8 + wm * 2 + mt) * 32 + lane) * 4);
            uint2 bf[8];
#pragma unroll
            for (int nt = 0; nt < 8; nt++)
                bf[nt] = *(const uint2*)(Bb + ((sl * 16 + wn * 8 + nt) * 32 + lane) * 2);
#pragma unroll
            for (int mt = 0; mt < 2; mt++)
#pragma unroll
                for (int nt = 0; nt < 8; nt++)
                    mma16(acc[mt][nt], (const uint32_t*)&af[mt], (const uint32_t*)&bf[nt]);
        }

        if (c + 1 < nchunk) store_chunk((c + 1) & 1);
        __syncthreads();
    }

    // epilogue: relu -> +residual(hx,ha fp16) -> relu -> pack fp16 into SMEM
#pragma unroll
    for (int mt = 0; mt < 2; mt++) {
        int Rb = wm * 32 + mt * 16 + group;
        int r0 = row_base + Rb;
#pragma unroll
        for (int nt = 0; nt < 8; nt++) {
            int col = wn * 64 + nt * 8 + tq * 2;
            float2 bv = *(const float2*)(b1 + col);
            float v00 = relu(acc[mt][nt][0] + bv.x);
            float v01 = relu(acc[mt][nt][1] + bv.y);
            float v10 = relu(acc[mt][nt][2] + bv.x);
            float v11 = relu(acc[mt][nt][3] + bv.y);
            if (r0 < M) {
                const uint32_t* cu = comb + (size_t)r0 * 128 + (col >> 1);
                float2 r1 = __half22float2(*(const __half2*)&cu[0]);
                float2 r2 = __half22float2(*(const __half2*)&cu[64]);
                v00 = relu(v00 + r1.x + r2.x);
                v01 = relu(v01 + r1.y + r2.y);
            }
            if (r0 + 8 < M) {
                const uint32_t* cu = comb + (size_t)(r0 + 8) * 128 + (col >> 1);
                float2 r1 = __half22float2(*(const __half2*)&cu[0]);
                float2 r2 = __half22float2(*(const __half2*)&cu[64]);
                v10 = relu(v10 + r1.x + r2.x);
                v11 = relu(v11 + r1.y + r2.y);
            }
            packH(Pk, Rb,     col, v00, v01);
            packH(Pk, Rb + 8, col, v10, v11);
        }
    }
    __syncthreads();

    // classifier: warp w covers rows w*16..w*16+15; N=40 -> 5 n-tiles
    float acc3[5][4];
#pragma unroll
    for (int j = 0; j < 5; j++)
#pragma unroll
        for (int q = 0; q < 4; q++) acc3[j][q] = 0.0f;

#pragma unroll
    for (int s = 0; s < 8; s++) {
        uint4 af = *(const uint4*)(Pk + ((s * 8 + w) * 32 + lane) * 4);
        uint2 bf[5];
#pragma unroll
        for (int nt = 0; nt < 5; nt++)
            bf[nt] = *(const uint2*)(Wcs + ((s * 5 + nt) * 32 + lane) * 2);
#pragma unroll
        for (int nt = 0; nt < 5; nt++)
            mma16(acc3[nt], (const uint32_t*)&af, (const uint32_t*)&bf[nt]);
    }

    int r0 = row_base + w * 16 + group;
#pragma unroll
    for (int nt = 0; nt < 5; nt++) {
        int col = nt * 8 + tq * 2;
        float2 bv = *(const float2*)(bc + col);
        if (r0 < M)
            *(float2*)(out + (size_t)r0 * NC + col) =
                make_float2(acc3[nt][0] + bv.x, acc3[nt][1] + bv.y);
        if (r0 + 8 < M)
            *(float2*)(out + (size_t)(r0 + 8) * NC + col) =
                make_float2(acc3[nt][2] + bv.x, acc3[nt][3] + bv.y);
    }
}

// ---------------- host launch ----------------
extern "C" void kernel_launch(void* const* d_in, const int* in_sizes, int n_in,
                              void* d_out, int out_size) {
    const float* x    = (const float*)d_in[0];
    const int*   ei   = (const int*)  d_in[1];
    const float* adj  = (const float*)d_in[2];
    const float* wx1  = (const float*)d_in[3];
    const float* bx1  = (const float*)d_in[4];
    const float* wx2  = (const float*)d_in[5];
    const float* bx2  = (const float*)d_in[6];
    const float* wa1  = (const float*)d_in[7];
    const float* ba1  = (const float*)d_in[8];
    const float* wa2  = (const float*)d_in[9];
    const float* ba2  = (const float*)d_in[10];
    const float* ww1  = (const float*)d_in[11];
    const float* bw1  = (const float*)d_in[12];
    const float* wc   = (const float*)d_in[13];
    const float* bc   = (const float*)d_in[14];
    float* out = (float*)d_out;

    uint32_t *comb, *agg, *wp;
    cudaGetSymbolAddress((void**)&comb, g_comb);
    cudaGetSymbolAddress((void**)&agg,  g_agg);
    cudaGetSymbolAddress((void**)&wp,   g_wp);

    cudaFuncSetAttribute(fused_mlp<0>, cudaFuncAttributeMaxDynamicSharedMemorySize, MLP_SMEM);
    cudaFuncSetAttribute(fused_mlp<1>, cudaFuncAttributeMaxDynamicSharedMemorySize, MLP_SMEM);
    cudaFuncSetAttribute(fused_final,  cudaFuncAttributeMaxDynamicSharedMemorySize, FIN_SMEM);

    int grid = (NN + 127) / 128;   // 782

    cudaStream_t sB;
    cudaStreamCreateWithFlags(&sB, cudaStreamNonBlocking);
    cudaEvent_t evPack, evX;
    cudaEventCreateWithFlags(&evPack, cudaEventDisableTiming);
    cudaEventCreateWithFlags(&evX,    cudaEventDisableTiming);

    // ---- main: weight packing (also zeroes histogram) ----
    pack_all<<<(119808 + 255) / 256, 256>>>(wx1, wx2, wa1, wa2, ww1, wc, wp);
    cudaEventRecord(evPack, 0);

    // ---- side: x-branch MLP (fp32 input x) ----
    cudaStreamWaitEvent(sB, evPack, 0);
    fused_mlp<0><<<grid, 256, MLP_SMEM, sB>>>(x, wp + WP_X1, bx1, wp + WP_X2, bx2,
                                              comb, INDIM, 128);
    cudaEventRecord(evX, sB);

    // ---- main: fp16 conversion + histogram, CSR build, gather ----
    prep_kernel<<<(NN * (HID / 4) + 255) / 256, 256>>>(adj, ei);
    scan1      <<<NBLK_SCAN, 1024>>>();
    scan2      <<<1, 128>>>();
    scan3      <<<(NN + 255) / 256, 256>>>();
    fill_kernel<<<(EE / 4 + 255) / 256, 256>>>(ei);
    gather_kernel<<<(NN * 32 + 255) / 256, 256>>>();

    // ---- main: a-branch MLP (fp16 input agg), then join and finish ----
    fused_mlp<1><<<grid, 256, MLP_SMEM>>>(agg, wp + WP_A1, ba1, wp + WP_A2, ba2,
                                          comb + 64, HID, 128);
    cudaStreamWaitEvent(0, evX, 0);
    fused_final<<<grid, 256, FIN_SMEM>>>(comb, wp + WP_W1, bw1, wp + WP_C, bc, out);
}

// round 14
// speedup vs baseline: 1.0912x; 1.0912x over previous
#include <cuda_runtime.h>
#include <cuda_bf16.h>
#include <cuda_fp16.h>
#include <cstdint>
#include <cstddef>

// LINKX forward: fp16 mma.sync GEMMs (fp32 accum), fp16 activations,
// CSR fp16 gather, x-branch MLP on a side stream, and a merged tail
// kernel (a-branch MLP + concat GEMM + residual + classifier in one).
//   hx = relu(x@wx1+bx1)@wx2+bx2                  (side stream)
//   agg = segment_mean(adj_embed[src] -> dst)     (CSR build + fp16 gather)
//   ha = relu(agg@wa1+ba1)@wa2+ba2                (fused_tail, SMEM-resident)
//   h  = relu(relu([hx,ha]@ww1+bw1) + hx + ha)    (fused_tail)
//   out = h@wc+bc                                 (fused_tail)

#define NN     100000
#define EE     1600000
#define INDIM  256
#define HID    128
#define NC     40

#define NBLK_SCAN 98   // ceil(NN/1024)

// ---------------- static scratch ----------------
__device__ uint32_t g_hx  [(size_t)NN * 64];   // hx fp16, row = 64 uints
__device__ uint32_t g_agg [(size_t)NN * 64];   // neighbour mean fp16
__device__ uint32_t g_z16 [(size_t)NN * 64];   // adj_embed fp16
__device__ uint32_t g_wp  [59904];             // fragment-packed fp16 weights
__device__ int      g_cnt [NN];
__device__ int      g_start[NN];
__device__ int      g_cur [NN];
__device__ int      g_bsum[NBLK_SCAN];
__device__ int      g_srcs[EE];

// packed-weight uint offsets (1 uint = half2)
#define WP_X1 0
#define WP_X2 16384
#define WP_A1 24576
#define WP_A2 32768
#define WP_W1 40960
#define WP_C  57344

// ---------------- helpers ----------------
__device__ __forceinline__ float relu(float v) { return fmaxf(v, 0.0f); }

// m16n8k16 fp16 MMA, fp32 accum
__device__ __forceinline__ void mma16(float* d, const uint32_t* a, const uint32_t* b) {
    asm volatile("mma.sync.aligned.m16n8k16.row.col.f32.f16.f16.f32 "
                 "{%0,%1,%2,%3}, {%4,%5,%6,%7}, {%8,%9}, {%0,%1,%2,%3};"
                 : "+f"(d[0]), "+f"(d[1]), "+f"(d[2]), "+f"(d[3])
                 : "r"(a[0]), "r"(a[1]), "r"(a[2]), "r"(a[3]),
                   "r"(b[0]), "r"(b[1]));
}

// Fragment-packed fp16 A layout (tile 128 rows x K cols), uint granularity.
__device__ __forceinline__ void packH(uint32_t* P, int R, int Ck, float v0, float v1) {
    int s = Ck >> 4, khi = (Ck >> 3) & 1, kp = (Ck & 7) >> 1;
    int mt = R >> 4, rg = (R >> 3) & 1, row8 = R & 7;
    __half2 h = __floats2half2_rn(v0, v1);
    P[(((s * 8 + mt) * 32 + row8 * 4 + kp) << 2) + khi * 2 + rg] = *(uint32_t*)&h;
}

__device__ __forceinline__ uint32_t readH(const uint32_t* P, int R, int Ck) {
    int s = Ck >> 4, khi = (Ck >> 3) & 1, kp = (Ck & 7) >> 1;
    int mt = R >> 4, rg = (R >> 3) & 1, row8 = R & 7;
    return P[(((s * 8 + mt) * 32 + row8 * 4 + kp) << 2) + khi * 2 + rg];
}

// ---------------- weight packing (B-fragment fp16 layout) ----------------
__device__ __forceinline__ void pack_one_h(const float* __restrict__ W,
                                           uint32_t* __restrict__ Pu, int idx) {
    int k = idx >> 7, n = idx & 127;
    int uidx = (((k >> 4) * 16 + (n >> 3)) * 32 + (n & 7) * 4 + ((k & 7) >> 1)) * 2
             + ((k >> 3) & 1);
    ((uint16_t*)Pu)[uidx * 2 + (k & 1)] = __half_as_ushort(__float2half_rn(W[idx]));
}

__global__ void pack_all(const float* __restrict__ wx1, const float* __restrict__ wx2,
                         const float* __restrict__ wa1, const float* __restrict__ wa2,
                         const float* __restrict__ ww1, const float* __restrict__ wc,
                         uint32_t* __restrict__ wp) {
    int i = blockIdx.x * blockDim.x + threadIdx.x;
    if (i < NN) g_cnt[i] = 0;
    if (i < 32768)       pack_one_h(wx1, wp + WP_X1, i);
    else if (i < 49152)  pack_one_h(wx2, wp + WP_X2, i - 32768);
    else if (i < 65536)  pack_one_h(wa1, wp + WP_A1, i - 49152);
    else if (i < 81920)  pack_one_h(wa2, wp + WP_A2, i - 65536);
    else if (i < 114688) pack_one_h(ww1, wp + WP_W1, i - 81920);
    else if (i < 119808) {
        int idx = i - 114688;
        int k = idx / 40, n = idx % 40;
        int uidx = (((k >> 4) * 5 + (n >> 3)) * 32 + (n & 7) * 4 + ((k & 7) >> 1)) * 2
                 + ((k >> 3) & 1);
        ((uint16_t*)(wp + WP_C))[uidx * 2 + (k & 1)] =
            __half_as_ushort(__float2half_rn(wc[idx]));
    }
}

// ---------------- adj_embed -> fp16 (side stream) ----------------
__global__ void conv_z(const float* __restrict__ z) {
    int i = blockIdx.x * blockDim.x + threadIdx.x;
    if (i >= NN * (HID / 4)) return;
    float4 v = ((const float4*)z)[i];
    __half2 h0 = __floats2half2_rn(v.x, v.y);
    __half2 h1 = __floats2half2_rn(v.z, v.w);
    uint2 u;
    u.x = *(uint32_t*)&h0;
    u.y = *(uint32_t*)&h1;
    ((uint2*)g_z16)[i] = u;
}

// ---------------- CSR build ----------------
__global__ void hist_kernel(const int* __restrict__ ei) {
    int t = blockIdx.x * blockDim.x + threadIdx.x;
    int e = t * 4;
    if (e + 4 > EE) return;
    int4 d = *(const int4*)(ei + EE + e);
    atomicAdd(&g_cnt[d.x], 1);
    atomicAdd(&g_cnt[d.y], 1);
    atomicAdd(&g_cnt[d.z], 1);
    atomicAdd(&g_cnt[d.w], 1);
}

__global__ void scan1() {
    __shared__ int sh[1024];
    int t  = threadIdx.x;
    int gi = blockIdx.x * 1024 + t;
    int v  = (gi < NN) ? g_cnt[gi] : 0;
    sh[t] = v;
    __syncthreads();
#pragma unroll
    for (int o = 1; o < 1024; o <<= 1) {
        int u = (t >= o) ? sh[t - o] : 0;
        __syncthreads();
        sh[t] += u;
        __syncthreads();
    }
    if (gi < NN) g_start[gi] = sh[t];
    if (t == 1023) g_bsum[blockIdx.x] = sh[1023];
}

// merged scan2+scan3: each block derives the 98-entry exclusive prefix itself
__global__ void scan3m() {
    __shared__ int bs[NBLK_SCAN];
    __shared__ int pre[NBLK_SCAN];
    int t = threadIdx.x;
    if (t < NBLK_SCAN) bs[t] = g_bsum[t];
    __syncthreads();
    if (t == 0) {
        int acc = 0;
        for (int j = 0; j < NBLK_SCAN; j++) { pre[j] = acc; acc += bs[j]; }
    }
    __syncthreads();
    int i = blockIdx.x * blockDim.x + t;
    if (i >= NN) return;
    int st = g_start[i] + pre[i >> 10] - g_cnt[i];
    g_start[i] = st;
    g_cur[i]   = st;
}

__global__ void fill_kernel(const int* __restrict__ ei) {
    int t = blockIdx.x * blockDim.x + threadIdx.x;
    int e = t * 4;
    if (e + 4 > EE) return;
    int4 s = *(const int4*)(ei + e);
    int4 d = *(const int4*)(ei + EE + e);
    g_srcs[atomicAdd(&g_cur[d.x], 1)] = s.x;
    g_srcs[atomicAdd(&g_cur[d.y], 1)] = s.y;
    g_srcs[atomicAdd(&g_cur[d.z], 1)] = s.z;
    g_srcs[atomicAdd(&g_cur[d.w], 1)] = s.w;
}

// ---------------- gather: one warp per node, fp16 in/out, fp32 accum --------
__global__ __launch_bounds__(256)
void gather_kernel() {
    int gw   = (blockIdx.x * blockDim.x + threadIdx.x) >> 5;
    int lane = threadIdx.x & 31;
    if (gw >= NN) return;
    int beg = g_start[gw];
    int dg  = g_cnt[gw];

    float2 a0 = make_float2(0.f, 0.f), b0 = make_float2(0.f, 0.f);
    float2 a1 = make_float2(0.f, 0.f), b1 = make_float2(0.f, 0.f);
    float2 a2 = make_float2(0.f, 0.f), b2 = make_float2(0.f, 0.f);
    float2 a3 = make_float2(0.f, 0.f), b3 = make_float2(0.f, 0.f);

    int e = 0;
    for (; e + 4 <= dg; e += 4) {
        int s0 = g_srcs[beg + e];
        int s1 = g_srcs[beg + e + 1];
        int s2 = g_srcs[beg + e + 2];
        int s3 = g_srcs[beg + e + 3];
        uint2 u0 = *((const uint2*)(g_z16 + (size_t)s0 * 64) + lane);
        uint2 u1 = *((const uint2*)(g_z16 + (size_t)s1 * 64) + lane);
        uint2 u2 = *((const uint2*)(g_z16 + (size_t)s2 * 64) + lane);
        uint2 u3 = *((const uint2*)(g_z16 + (size_t)s3 * 64) + lane);
        float2 f;
        f = __half22float2(*(__half2*)&u0.x); a0.x += f.x; a0.y += f.y;
        f = __half22float2(*(__half2*)&u0.y); b0.x += f.x; b0.y += f.y;
        f = __half22float2(*(__half2*)&u1.x); a1.x += f.x; a1.y += f.y;
        f = __half22float2(*(__half2*)&u1.y); b1.x += f.x; b1.y += f.y;
        f = __half22float2(*(__half2*)&u2.x); a2.x += f.x; a2.y += f.y;
        f = __half22float2(*(__half2*)&u2.y); b2.x += f.x; b2.y += f.y;
        f = __half22float2(*(__half2*)&u3.x); a3.x += f.x; a3.y += f.y;
        f = __half22float2(*(__half2*)&u3.y); b3.x += f.x; b3.y += f.y;
    }
    for (; e < dg; e++) {
        int s0 = g_srcs[beg + e];
        uint2 u0 = *((const uint2*)(g_z16 + (size_t)s0 * 64) + lane);
        float2 f;
        f = __half22float2(*(__half2*)&u0.x); a0.x += f.x; a0.y += f.y;
        f = __half22float2(*(__half2*)&u0.y); b0.x += f.x; b0.y += f.y;
    }

    float inv = 1.0f / (float)max(dg, 1);
    __half2 h0 = __floats2half2_rn((a0.x + a1.x + a2.x + a3.x) * inv,
                                   (a0.y + a1.y + a2.y + a3.y) * inv);
    __half2 h1 = __floats2half2_rn((b0.x + b1.x + b2.x + b3.x) * inv,
                                   (b0.y + b1.y + b2.y + b3.y) * inv);
    uint2 u;
    u.x = *(uint32_t*)&h0;
    u.y = *(uint32_t*)&h1;
    *((uint2*)(g_agg + (size_t)gw * 64) + lane) = u;
}

// ---------------- x-branch fused 2-layer MLP (fp32 input) ----------------
// Cout(fp16, ldcu uints) = relu(A@W1+b1)@W2 + b2.
#define MLP_SMEM (8192 * 4)

__global__ __launch_bounds__(256, 2)
void fused_mlp_x(const float* __restrict__ A, const uint32_t* __restrict__ W1p,
                 const float* __restrict__ b1, const uint32_t* __restrict__ W2p,
                 const float* __restrict__ b2, uint32_t* __restrict__ Cout,
                 int K1, int ldcu) {
    extern __shared__ uint32_t smu[];
    uint32_t* Pk = smu;

    int tid  = threadIdx.x;
    int lane = tid & 31;
    int w    = tid >> 5;
    int wm   = w >> 1;
    int wn   = w & 1;
    int group = lane >> 2;
    int tq    = lane & 3;
    int row_base = blockIdx.x * 128;
    const int M = NN;

    float acc[2][8][4];
#pragma unroll
    for (int i = 0; i < 2; i++)
#pragma unroll
        for (int j = 0; j < 8; j++)
#pragma unroll
            for (int q = 0; q < 4; q++) acc[i][j][q] = 0.0f;

    int wf_r[4], wf_c4[4];
#pragma unroll
    for (int i = 0; i < 4; i++) {
        int f = tid + i * 256;
        wf_r[i]  = f >> 3;
        wf_c4[i] = (f & 7) << 2;
    }

    float4 stA[4];
    uint4  stB[2];
    int nchunk = K1 >> 5;

    auto load_chunk = [&](int c) {
#pragma unroll
        for (int i = 0; i < 4; i++) {
            int gr = row_base + wf_r[i];
            float4 v = make_float4(0.f, 0.f, 0.f, 0.f);
            if (gr < M)
                v = *(const float4*)(A + (size_t)gr * K1 + (c << 5) + wf_c4[i]);
            stA[i] = v;
        }
        const uint4* bsrc = (const uint4*)(W1p + c * 2048);
#pragma unroll
        for (int i = 0; i < 2; i++) stB[i] = bsrc[tid + i * 256];
    };

    auto store_chunk = [&](int b) {
        uint32_t* Ab = smu + b * 4096;
        uint32_t* Bb = smu + b * 4096 + 2048;
#pragma unroll
        for (int i = 0; i < 4; i++) {
            int r = wf_r[i], c4 = wf_c4[i];
            int sl  = c4 >> 4;
            int khi = (c4 >> 3) & 1;
            int kp  = (c4 & 7) >> 1;
            int mt  = r >> 4, rg = (r >> 3) & 1, row8 = r & 7;
            uint32_t base = (((sl * 8 + mt) * 32 + row8 * 4 + kp) << 2) + khi * 2 + rg;
            __half2 h0 = __floats2half2_rn(stA[i].x, stA[i].y);
            __half2 h1 = __floats2half2_rn(stA[i].z, stA[i].w);
            Ab[base]     = *(uint32_t*)&h0;
            Ab[base + 4] = *(uint32_t*)&h1;
        }
        ((uint4*)Bb)[tid]       = stB[0];
        ((uint4*)Bb)[tid + 256] = stB[1];
    };

    load_chunk(0);
    store_chunk(0);
    __syncthreads();

    for (int c = 0; c < nchunk; c++) {
        int b = c & 1;
        if (c + 1 < nchunk) load_chunk(c + 1);

        const uint32_t* Ab = smu + b * 4096;
        const uint32_t* Bb = smu + b * 4096 + 2048;
#pragma unroll
        for (int sl = 0; sl < 2; sl++) {
            uint4 af[2];
#pragma unroll
            for (int mt = 0; mt < 2; mt++)
                af[mt] = *(const uint4*)(Ab + ((sl * 8 + wm * 2 + mt) * 32 + lane) * 4);
            uint2 bf[8];
#pragma unroll
            for (int nt = 0; nt < 8; nt++)
                bf[nt] = *(const uint2*)(Bb + ((sl * 16 + wn * 8 + nt) * 32 + lane) * 2);
#pragma unroll
            for (int mt = 0; mt < 2; mt++)
#pragma unroll
                for (int nt = 0; nt < 8; nt++)
                    mma16(acc[mt][nt], (const uint32_t*)&af[mt], (const uint32_t*)&bf[nt]);
        }

        if (c + 1 < nchunk) store_chunk((c + 1) & 1);
        __syncthreads();
    }

    // stage-1 epilogue -> Pk (aliased)
#pragma unroll
    for (int mt = 0; mt < 2; mt++) {
        int Rb = wm * 32 + mt * 16 + group;
#pragma unroll
        for (int nt = 0; nt < 8; nt++) {
            int col = wn * 64 + nt * 8 + tq * 2;
            float2 bv = *(const float2*)(b1 + col);
            packH(Pk, Rb,     col, relu(acc[mt][nt][0] + bv.x),
                                   relu(acc[mt][nt][1] + bv.y));
            packH(Pk, Rb + 8, col, relu(acc[mt][nt][2] + bv.x),
                                   relu(acc[mt][nt][3] + bv.y));
        }
    }
    __syncthreads();

    // stage 2: Pk @ W2 (global / L1)
    float acc2[2][8][4];
#pragma unroll
    for (int i = 0; i < 2; i++)
#pragma unroll
        for (int j = 0; j < 8; j++)
#pragma unroll
            for (int q = 0; q < 4; q++) acc2[i][j][q] = 0.0f;

    const uint2* W2f = (const uint2*)W2p;
#pragma unroll
    for (int s = 0; s < 8; s++) {
        uint4 af[2];
#pragma unroll
        for (int mt = 0; mt < 2; mt++)
            af[mt] = *(const uint4*)(Pk + ((s * 8 + wm * 2 + mt) * 32 + lane) * 4);
        uint2 bf[8];
#pragma unroll
        for (int nt = 0; nt < 8; nt++)
            bf[nt] = __ldg(W2f + (s * 16 + wn * 8 + nt) * 32 + lane);
#pragma unroll
        for (int mt = 0; mt < 2; mt++)
#pragma unroll
            for (int nt = 0; nt < 8; nt++)
                mma16(acc2[mt][nt], (const uint32_t*)&af[mt], (const uint32_t*)&bf[nt]);
    }

#pragma unroll
    for (int mt = 0; mt < 2; mt++) {
        int r0 = row_base + wm * 32 + mt * 16 + group;
#pragma unroll
        for (int nt = 0; nt < 8; nt++) {
            int col = wn * 64 + nt * 8 + tq * 2;
            float2 bv = *(const float2*)(b2 + col);
            if (r0 < M) {
                __half2 h = __floats2half2_rn(acc2[mt][nt][0] + bv.x,
                                              acc2[mt][nt][1] + bv.y);
                Cout[(size_t)r0 * ldcu + (col >> 1)] = *(uint32_t*)&h;
            }
            if (r0 + 8 < M) {
                __half2 h = __floats2half2_rn(acc2[mt][nt][2] + bv.x,
                                              acc2[mt][nt][3] + bv.y);
                Cout[(size_t)(r0 + 8) * ldcu + (col >> 1)] = *(uint32_t*)&h;
            }
        }
    }
}

// ---------------- fused tail: a-branch MLP + concat GEMM + classifier ------
// SMEM: RA 8192 uints (double buffers / Pk, aliased), PB 8192 uints (ha
// packed as A-fragment steps for K 128..255), Wcs 2560 uints. 75776 B total.
#define TAIL_SMEM ((8192 + 8192 + 2560) * 4)

__global__ __launch_bounds__(256, 2)
void fused_tail(const uint32_t* __restrict__ agg,
                const uint32_t* __restrict__ W1a, const float* __restrict__ b1a,
                const uint32_t* __restrict__ W2a, const float* __restrict__ b2a,
                const uint32_t* __restrict__ hx,
                const uint32_t* __restrict__ Ww1, const float* __restrict__ bw1,
                const uint32_t* __restrict__ Wcp, const float* __restrict__ bc,
                float* __restrict__ out) {
    extern __shared__ uint32_t smu[];
    uint32_t* RA  = smu;           // mainloop buffers / Pk
    uint32_t* PB  = smu + 8192;    // ha fragment-packed (local steps 0..7)
    uint32_t* Wcs = smu + 16384;

    int tid  = threadIdx.x;
    int lane = tid & 31;
    int w    = tid >> 5;
    int wm   = w >> 1;
    int wn   = w & 1;
    int group = lane >> 2;
    int tq    = lane & 3;
    int row_base = blockIdx.x * 128;
    const int M = NN;

    for (int i = tid; i < 640; i += 256)
        ((uint4*)Wcs)[i] = ((const uint4*)Wcp)[i];

    int wf_r[4], wf_c4[4];
#pragma unroll
    for (int i = 0; i < 4; i++) {
        int f = tid + i * 256;
        wf_r[i]  = f >> 3;
        wf_c4[i] = (f & 7) << 2;
    }

    uint2 stAu[4];
    uint4 stB[2];

    // generic fp16-A chunk loader/storer (A rows = 64 uints)
    auto load_chunk = [&](const uint32_t* Asrc, const uint32_t* W1p, int c) {
#pragma unroll
        for (int i = 0; i < 4; i++) {
            int gr = row_base + wf_r[i];
            uint2 u = make_uint2(0u, 0u);
            if (gr < M)
                u = *(const uint2*)(Asrc + (size_t)gr * 64 + (c << 4) + (wf_c4[i] >> 1));
            stAu[i] = u;
        }
        const uint4* bsrc = (const uint4*)(W1p + c * 2048);
#pragma unroll
        for (int i = 0; i < 2; i++) stB[i] = bsrc[tid + i * 256];
    };

    auto store_chunk = [&](int b) {
        uint32_t* Ab = RA + b * 4096;
        uint32_t* Bb = RA + b * 4096 + 2048;
#pragma unroll
        for (int i = 0; i < 4; i++) {
            int r = wf_r[i], c4 = wf_c4[i];
            int sl  = c4 >> 4;
            int khi = (c4 >> 3) & 1;
            int kp  = (c4 & 7) >> 1;
            int mt  = r >> 4, rg = (r >> 3) & 1, row8 = r & 7;
            uint32_t base = (((sl * 8 + mt) * 32 + row8 * 4 + kp) << 2) + khi * 2 + rg;
            Ab[base]     = stAu[i].x;
            Ab[base + 4] = stAu[i].y;
        }
        ((uint4*)Bb)[tid]       = stB[0];
        ((uint4*)Bb)[tid + 256] = stB[1];
    };

    auto mma_chunk = [&](int b, float acc_[2][8][4]) {
        const uint32_t* Ab = RA + b * 4096;
        const uint32_t* Bb = RA + b * 4096 + 2048;
#pragma unroll
        for (int sl = 0; sl < 2; sl++) {
            uint4 af[2];
#pragma unroll
            for (int mt = 0; mt < 2; mt++)
                af[mt] = *(const uint4*)(Ab + ((sl * 8 + wm * 2 + mt) * 32 + lane) * 4);
            uint2 bf[8];
#pragma unroll
            for (int nt = 0; nt < 8; nt++)
                bf[nt] = *(const uint2*)(Bb + ((sl * 16 + wn * 8 + nt) * 32 + lane) * 2);
#pragma unroll
            for (int mt = 0; mt < 2; mt++)
#pragma unroll
                for (int nt = 0; nt < 8; nt++)
                    mma16(acc_[mt][nt], (const uint32_t*)&af[mt], (const uint32_t*)&bf[nt]);
        }
    };

    // ===== phase 1: a-branch stage 1 (agg @ W1a, K=128) =====
    float acc[2][8][4];
#pragma unroll
    for (int i = 0; i < 2; i++)
#pragma unroll
        for (int j = 0; j < 8; j++)
#pragma unroll
            for (int q = 0; q < 4; q++) acc[i][j][q] = 0.0f;

    load_chunk(agg, W1a, 0);
    store_chunk(0);
    __syncthreads();
    for (int c = 0; c < 4; c++) {
        if (c + 1 < 4) load_chunk(agg, W1a, c + 1);
        mma_chunk(c & 1, acc);
        if (c + 1 < 4) store_chunk((c + 1) & 1);
        __syncthreads();
    }

    // stage-1 epi -> Pk (= RA, mainloop dead)
#pragma unroll
    for (int mt = 0; mt < 2; mt++) {
        int Rb = wm * 32 + mt * 16 + group;
#pragma unroll
        for (int nt = 0; nt < 8; nt++) {
            int col = wn * 64 + nt * 8 + tq * 2;
            float2 bv = *(const float2*)(b1a + col);
            packH(RA, Rb,     col, relu(acc[mt][nt][0] + bv.x),
                                   relu(acc[mt][nt][1] + bv.y));
            packH(RA, Rb + 8, col, relu(acc[mt][nt][2] + bv.x),
                                   relu(acc[mt][nt][3] + bv.y));
        }
    }
    __syncthreads();

    // ===== phase 2: a-branch stage 2 -> ha, packed into PB =====
    float acc2[2][8][4];
#pragma unroll
    for (int i = 0; i < 2; i++)
#pragma unroll
        for (int j = 0; j < 8; j++)
#pragma unroll
            for (int q = 0; q < 4; q++) acc2[i][j][q] = 0.0f;

    const uint2* W2f = (const uint2*)W2a;
#pragma unroll
    for (int s = 0; s < 8; s++) {
        uint4 af[2];
#pragma unroll
        for (int mt = 0; mt < 2; mt++)
            af[mt] = *(const uint4*)(RA + ((s * 8 + wm * 2 + mt) * 32 + lane) * 4);
        uint2 bf[8];
#pragma unroll
        for (int nt = 0; nt < 8; nt++)
            bf[nt] = __ldg(W2f + (s * 16 + wn * 8 + nt) * 32 + lane);
#pragma unroll
        for (int mt = 0; mt < 2; mt++)
#pragma unroll
            for (int nt = 0; nt < 8; nt++)
                mma16(acc2[mt][nt], (const uint32_t*)&af[mt], (const uint32_t*)&bf[nt]);
    }

    // ha = acc2 + b2a -> PB (fragment layout, local col 0..127)
#pragma unroll
    for (int mt = 0; mt < 2; mt++) {
        int Rb = wm * 32 + mt * 16 + group;
#pragma unroll
        for (int nt = 0; nt < 8; nt++) {
            int col = wn * 64 + nt * 8 + tq * 2;
            float2 bv = *(const float2*)(b2a + col);
            packH(PB, Rb,     col, acc2[mt][nt][0] + bv.x, acc2[mt][nt][1] + bv.y);
            packH(PB, Rb + 8, col, acc2[mt][nt][2] + bv.x, acc2[mt][nt][3] + bv.y);
        }
    }
    __syncthreads();    // Pk(RA) reads done, PB written -> safe to reuse RA

    // ===== phase 3: concat GEMM: [hx | ha] @ ww1, K=256 =====
#pragma unroll
    for (int i = 0; i < 2; i++)
#pragma unroll
        for (int j = 0; j < 8; j++)
#pragma unroll
            for (int q = 0; q < 4; q++) acc[i][j][q] = 0.0f;

    load_chunk(hx, Ww1, 0);
    store_chunk(0);
    __syncthreads();
    for (int c = 0; c < 4; c++) {            // steps 0..7 (hx)
        if (c + 1 < 4) load_chunk(hx, Ww1, c + 1);
        mma_chunk(c & 1, acc);
        if (c + 1 < 4) store_chunk((c + 1) & 1);
        __syncthreads();
    }
    const uint2* W1f = (const uint2*)Ww1;
#pragma unroll
    for (int s2 = 0; s2 < 8; s2++) {         // steps 8..15 (ha from PB)
        uint4 af[2];
#pragma unroll
        for (int mt = 0; mt < 2; mt++)
            af[mt] = *(const uint4*)(PB + ((s2 * 8 + wm * 2 + mt) * 32 + lane) * 4);
        uint2 bf[8];
#pragma unroll
        for (int nt = 0; nt < 8; nt++)
            bf[nt] = __ldg(W1f + ((s2 + 8) * 16 + wn * 8 + nt) * 32 + lane);
#pragma unroll
        for (int mt = 0; mt < 2; mt++)
#pragma unroll
            for (int nt = 0; nt < 8; nt++)
                mma16(acc[mt][nt], (const uint32_t*)&af[mt], (const uint32_t*)&bf[nt]);
    }

    // epilogue: relu -> + hx(global) + ha(PB) -> relu -> pack into Pk(RA)
#pragma unroll
    for (int mt = 0; mt < 2; mt++) {
        int Rb = wm * 32 + mt * 16 + group;
        int r0 = row_base + Rb;
#pragma unroll
        for (int nt = 0; nt < 8; nt++) {
            int col = wn * 64 + nt * 8 + tq * 2;
            float2 bv = *(const float2*)(bw1 + col);
            float v00 = relu(acc[mt][nt][0] + bv.x);
            float v01 = relu(acc[mt][nt][1] + bv.y);
            float v10 = relu(acc[mt][nt][2] + bv.x);
            float v11 = relu(acc[mt][nt][3] + bv.y);
            {
                float2 ra = __half22float2(*(__half2*)&(
                    (uint32_t&)*(uint32_t*)&PB[0]));  // placeholder avoided below
            }
            if (r0 < M) {
                uint32_t hu = hx[(size_t)r0 * 64 + (col >> 1)];
                float2 r1 = __half22float2(*(__half2*)&hu);
                uint32_t au = readH(PB, Rb, col);
                float2 r2 = __half22float2(*(__half2*)&au);
                v00 = relu(v00 + r1.x + r2.x);
                v01 = relu(v01 + r1.y + r2.y);
            }
            if (r0 + 8 < M) {
                uint32_t hu = hx[(size_t)(r0 + 8) * 64 + (col >> 1)];
                float2 r1 = __half22float2(*(__half2*)&hu);
                uint32_t au = readH(PB, Rb + 8, col);
                float2 r2 = __half22float2(*(__half2*)&au);
                v10 = relu(v10 + r1.x + r2.x);
                v11 = relu(v11 + r1.y + r2.y);
            }
            packH(RA, Rb,     col, v00, v01);
            packH(RA, Rb + 8, col, v10, v11);
        }
    }
    __syncthreads();

    // ===== phase 4: classifier (Pk=RA @ Wcs), warp w -> rows w*16..w*16+15
    float acc3[5][4];
#pragma unroll
    for (int j = 0; j < 5; j++)
#pragma unroll
        for (int q = 0; q < 4; q++) acc3[j][q] = 0.0f;

#pragma unroll
    for (int s = 0; s < 8; s++) {
        uint4 af = *(const uint4*)(RA + ((s * 8 + w) * 32 + lane) * 4);
        uint2 bf[5];
#pragma unroll
        for (int nt = 0; nt < 5; nt++)
            bf[nt] = *(const uint2*)(Wcs + ((s * 5 + nt) * 32 + lane) * 2);
#pragma unroll
        for (int nt = 0; nt < 5; nt++)
            mma16(acc3[nt], (const uint32_t*)&af, (const uint32_t*)&bf[nt]);
    }

    int r0c = row_base + w * 16 + group;
#pragma unroll
    for (int nt = 0; nt < 5; nt++) {
        int col = nt * 8 + tq * 2;
        float2 bv = *(const float2*)(bc + col);
        if (r0c < M)
            *(float2*)(out + (size_t)r0c * NC + col) =
                make_float2(acc3[nt][0] + bv.x, acc3[nt][1] + bv.y);
        if (r0c + 8 < M)
            *(float2*)(out + (size_t)(r0c + 8) * NC + col) =
                make_float2(acc3[nt][2] + bv.x, acc3[nt][3] + bv.y);
    }
}

// ---------------- host launch ----------------
extern "C" void kernel_launch(void* const* d_in, const int* in_sizes, int n_in,
                              void* d_out, int out_size) {
    const float* x    = (const float*)d_in[0];
    const int*   ei   = (const int*)  d_in[1];
    const float* adj  = (const float*)d_in[2];
    const float* wx1  = (const float*)d_in[3];
    const float* bx1  = (const float*)d_in[4];
    const float* wx2  = (const float*)d_in[5];
    const float* bx2  = (const float*)d_in[6];
    const float* wa1  = (const float*)d_in[7];
    const float* ba1  = (const float*)d_in[8];
    const float* wa2  = (const float*)d_in[9];
    const float* ba2  = (const float*)d_in[10];
    const float* ww1  = (const float*)d_in[11];
    const float* bw1  = (const float*)d_in[12];
    const float* wc   = (const float*)d_in[13];
    const float* bc   = (const float*)d_in[14];
    float* out = (float*)d_out;

    uint32_t *hx, *agg, *wp;
    cudaGetSymbolAddress((void**)&hx,  g_hx);
    cudaGetSymbolAddress((void**)&agg, g_agg);
    cudaGetSymbolAddress((void**)&wp,  g_wp);

    cudaFuncSetAttribute(fused_mlp_x, cudaFuncAttributeMaxDynamicSharedMemorySize, MLP_SMEM);
    cudaFuncSetAttribute(fused_tail,  cudaFuncAttributeMaxDynamicSharedMemorySize, TAIL_SMEM);

    int grid = (NN + 127) / 128;   // 782

    cudaStream_t sB;
    cudaStreamCreateWithFlags(&sB, cudaStreamNonBlocking);
    cudaEvent_t evPack, evConv, evX;
    cudaEventCreateWithFlags(&evPack, cudaEventDisableTiming);
    cudaEventCreateWithFlags(&evConv, cudaEventDisableTiming);
    cudaEventCreateWithFlags(&evX,    cudaEventDisableTiming);

    // ---- main: weight packing (also zeroes histogram) ----
    pack_all<<<(119808 + 255) / 256, 256>>>(wx1, wx2, wa1, wa2, ww1, wc, wp);
    cudaEventRecord(evPack, 0);

    // ---- side: conv adj->fp16, then x-branch MLP ----
    cudaStreamWaitEvent(sB, evPack, 0);
    conv_z<<<(NN * (HID / 4) + 255) / 256, 256, 0, sB>>>(adj);
    cudaEventRecord(evConv, sB);
    fused_mlp_x<<<grid, 256, MLP_SMEM, sB>>>(x, wp + WP_X1, bx1, wp + WP_X2, bx2,
                                             hx, INDIM, 64);
    cudaEventRecord(evX, sB);

    // ---- main: histogram, scans, fill ----
    hist_kernel<<<(EE / 4 + 255) / 256, 256>>>(ei);
    scan1 <<<NBLK_SCAN, 1024>>>();
    scan3m<<<(NN + 255) / 256, 256>>>();
    fill_kernel<<<(EE / 4 + 255) / 256, 256>>>(ei);

    // ---- main: gather (needs conv), then fused tail (needs hx) ----
    cudaStreamWaitEvent(0, evConv, 0);
    gather_kernel<<<(NN * 32 + 255) / 256, 256>>>();
    cudaStreamWaitEvent(0, evX, 0);
    fused_tail<<<grid, 256, TAIL_SMEM>>>(agg, wp + WP_A1, ba1, wp + WP_A2, ba2,
                                         hx, wp + WP_W1, bw1, wp + WP_C, bc, out);
}